// round 16
// baseline (speedup 1.0000x reference)
#include <cuda_runtime.h>
#include <cuda_bf16.h>
#include <cstdint>
#include <math.h>

#define TMAX 69632

__constant__ int   c_adj[17]  = {0x93,0x7,0xE,0xC,0x31,0x70,0x60,0x181,0x4B80,
                                 0x700,0x600,0x1900,0x3800,0x3000,0xC100,0x1C000,0x18000};
__constant__ float c_deg[17]  = {4,3,3,2,3,3,2,3,5,3,2,3,3,2,3,3,2};
__constant__ int   c_hop[17]  = {0,1,4,7,2,5,8,3,6,9,11,14,10,12,15,13,16};
__constant__ int   c_graph[17]= {0,1,4,7,2,5,8,3,6,9,12,10,13,15,11,14,16};
__constant__ int   c_bpe[17]  = {0,1,2,0,1,2,0,1,2,0,3,4,0,3,4,3,4};

__device__ __nv_bfloat16 g_bufA[(size_t)TMAX*1024];
__device__ __nv_bfloat16 g_bufB[(size_t)TMAX*768];
__device__ __nv_bfloat16 g_bufC[(size_t)TMAX*512];
__device__ __nv_bfloat16 g_bufD[(size_t)TMAX*256];
__device__ float g_res1[(size_t)TMAX*256];
__device__ float g_res2[(size_t)TMAX*256];
__device__ float g_x1  [(size_t)TMAX*256];
__device__ float g_tmpf[(size_t)TMAX*256];
__device__ __nv_bfloat16 g_wt[1441792];

__device__ __forceinline__ float gelu_t(float x) {
    float x3 = x*x*x;
    return 0.5f*x*(1.f + tanhf(0.7978845608028654f*(x + 0.044715f*x3)));
}
__device__ __forceinline__ float silu_f(float x) { return x / (1.f + expf(-x)); }
__device__ __forceinline__ float softplus_f(float x) { return x > 20.f ? x : log1pf(expf(x)); }

struct GP {
    const __nv_bfloat16* A;
    const __nv_bfloat16* Wt;
    const float* bias;
    const float* add1;
    const float* add2;
    const float* cw;
    const float* cb;
    float* outf;
    __nv_bfloat16* outh;
};

__device__ __forceinline__ void mma_bf16(float* d, const uint32_t* a,
                                         uint32_t b0, uint32_t b1)
{
    asm volatile(
        "mma.sync.aligned.m16n8k16.row.col.f32.bf16.bf16.f32 "
        "{%0,%1,%2,%3}, {%4,%5,%6,%7}, {%8,%9}, {%0,%1,%2,%3};\n"
        : "+f"(d[0]), "+f"(d[1]), "+f"(d[2]), "+f"(d[3])
        : "r"(a[0]), "r"(a[1]), "r"(a[2]), "r"(a[3]), "r"(b0), "r"(b1));
}

// swizzled byte offset of 16B chunk (r, c) within a [128][32]bf16 tile
__device__ __forceinline__ uint32_t sw_off(int r, int c)
{
    return (uint32_t)((r*4 + (c ^ ((r>>1)&3))) << 4);
}

__device__ __forceinline__ void cp16(uint32_t smem, const void* gmem)
{
    asm volatile("cp.async.cg.shared.global [%0], [%1], 16;\n" :: "r"(smem), "l"(gmem));
}

// vectorized epilogue: v0 at column c (even), v1 at c+1
template<int N, int EPI>
__device__ __forceinline__ void epi_store(const GP& p, int t, int c,
                                          float v0, float v1, int Ttot)
{
    if (t >= Ttot) return;
    if (EPI == 0) {
        __nv_bfloat162 r = __floats2bfloat162_rn(v0, v1);
        *reinterpret_cast<__nv_bfloat162*>(p.outh + (size_t)t*N + c) = r;
    }
    if (EPI == 1) {
        float2 bb = *reinterpret_cast<const float2*>(p.bias + c);
        v0 = gelu_t(v0 + bb.x);
        v1 = gelu_t(v1 + bb.y);
        __nv_bfloat162 r = __floats2bfloat162_rn(v0, v1);
        *reinterpret_cast<__nv_bfloat162*>(p.outh + (size_t)t*N + c) = r;
    }
    if (EPI == 2) {
        float2 bb = *reinterpret_cast<const float2*>(p.bias + c);
        float2 a1 = *reinterpret_cast<const float2*>(p.add1 + (size_t)t*256 + c);
        float2 o;
        o.x = v0 + bb.x + a1.x;
        o.y = v1 + bb.y + a1.y;
        *reinterpret_cast<float2*>(p.outf + (size_t)t*256 + c) = o;
    }
    if (EPI == 3) {
        float2 o; o.x = v0; o.y = v1;
        *reinterpret_cast<float2*>(p.outf + (size_t)t*256 + c) = o;
    }
    if (EPI == 4) {
        if (c < 512) {
            float2 cw = *reinterpret_cast<const float2*>(p.cw + c);
            float2 cb = *reinterpret_cast<const float2*>(p.cb + c);
            v0 = silu_f(fmaf(v0, cw.x, cb.x));
            v1 = silu_f(fmaf(v1, cw.y, cb.y));
        } else {
            v0 = silu_f(v0);
            v1 = silu_f(v1);
        }
        __nv_bfloat162 r = __floats2bfloat162_rn(v0, v1);
        *reinterpret_cast<__nv_bfloat162*>(p.outh + (size_t)t*1024 + c) = r;
    }
    if (EPI == 5) {
        float2 bb = *reinterpret_cast<const float2*>(p.bias + c);
        float2 a1 = *reinterpret_cast<const float2*>(p.add1 + (size_t)t*256 + c);
        float2 a2 = *reinterpret_cast<const float2*>(p.add2 + (size_t)t*256 + c);
        float2 o;
        o.x = v0 + bb.x + a1.x + a2.x;
        o.y = v1 + bb.y + a1.y + a2.y;
        *reinterpret_cast<float2*>(p.outf + (size_t)t*256 + c) = o;
    }
}

// ---- GEMM: CTA tile 128x128, 8 warps (4m x 2n), warp tile 32x64 ------------
// 5-stage cp.async ring in dynamic smem (80 KB). Register-bound at 2 CTA/SM,
// so the extra smem is free occupancy-wise.
#define GSTAGES 5
#define GSMEM   (GSTAGES * 8192 * 2)

template<int K, int N, int EPI>
__global__ void __launch_bounds__(256, 2) gemm_tc(GP p, int Ttot)
{
    extern __shared__ __nv_bfloat16 gsm[];
    const int tid  = threadIdx.x;
    const int lane = tid & 31;
    const int wid  = tid >> 5;
    const int wm = wid & 3;
    const int wn = wid >> 2;
    const int mBase = blockIdx.y * 128;
    const int nBase = blockIdx.x * 128;
    const int g  = lane >> 2;
    const int tq = lane & 3;
    constexpr int NT_TILES = K / 32;

    const uint32_t baseA = (uint32_t)__cvta_generic_to_shared(&gsm[0]);
    const uint32_t baseB = baseA + (uint32_t)(GSTAGES * 8192);

    const int r0s = tid >> 2,        c0s = tid & 3;
    const int r1s = (tid+256) >> 2,  c1s = tid & 3;
    int gr0 = mBase + r0s; if (gr0 >= Ttot) gr0 = Ttot - 1;
    int gr1 = mBase + r1s; if (gr1 >= Ttot) gr1 = Ttot - 1;
    const __nv_bfloat16* a0p = p.A  + (size_t)gr0*K          + c0s*8;
    const __nv_bfloat16* a1p = p.A  + (size_t)gr1*K          + c1s*8;
    const __nv_bfloat16* b0p = p.Wt + (size_t)(nBase+r0s)*K  + c0s*8;
    const __nv_bfloat16* b1p = p.Wt + (size_t)(nBase+r1s)*K  + c1s*8;

    // hoisted swizzled offsets (stage-relative)
    const uint32_t cp0 = sw_off(r0s, c0s);
    const uint32_t cp1 = sw_off(r1s, c1s);
    uint32_t aoff[2][2];   // [mi][ks]
    for (int mi = 0; mi < 2; ++mi)
        for (int ks = 0; ks < 2; ++ks) {
            const int rr = wm*32 + mi*16 + (lane & 15);
            const int cc = 2*ks + (lane >> 4);
            aoff[mi][ks] = sw_off(rr, cc);
        }
    uint32_t boff[4][2];   // [nb4][ks]
    for (int nb4 = 0; nb4 < 4; ++nb4)
        for (int ks = 0; ks < 2; ++ks) {
            const int midx = lane >> 3;
            const int rr = wn*64 + nb4*16 + (midx>>1)*8 + (lane & 7);
            const int cc = 2*ks + (midx & 1);
            boff[nb4][ks] = sw_off(rr, cc);
        }

    float acc[2][8][4];
    for (int a = 0; a < 2; ++a)
        for (int b = 0; b < 8; ++b)
            for (int c = 0; c < 4; ++c)
                acc[a][b][c] = 0.f;

    // prologue: issue tiles 0..GSTAGES-2 (one commit group each)
#pragma unroll
    for (int t = 0; t < GSTAGES-1; ++t) {
        if (t < NT_TILES) {
            const int koff = t*32;
            const uint32_t sA = baseA + (uint32_t)(t % GSTAGES)*8192u;
            const uint32_t sB = baseB + (uint32_t)(t % GSTAGES)*8192u;
            cp16(sA + cp0, a0p + koff);
            cp16(sA + cp1, a1p + koff);
            cp16(sB + cp0, b0p + koff);
            cp16(sB + cp1, b1p + koff);
        }
        asm volatile("cp.async.commit_group;\n");
    }

#pragma unroll
    for (int t = 0; t < NT_TILES; ++t) {
        // RAW: pending groups {t..t+GSTAGES-2}; wait to <=GSTAGES-2 pending
        // => oldest (tile t) landed.
        asm volatile("cp.async.wait_group %0;\n" :: "n"(GSTAGES-2));
        __syncthreads();
        // WAR: cp into stage (t+GSTAGES-1)%GSTAGES == (t-1)%GSTAGES — its
        // readers ran in iteration t-1, all finished before the barrier above.
        {
            const int tn = t + GSTAGES - 1;
            if (tn < NT_TILES) {
                const int koff = tn*32;
                const uint32_t sA = baseA + (uint32_t)(tn % GSTAGES)*8192u;
                const uint32_t sB = baseB + (uint32_t)(tn % GSTAGES)*8192u;
                cp16(sA + cp0, a0p + koff);
                cp16(sA + cp1, a1p + koff);
                cp16(sB + cp0, b0p + koff);
                cp16(sB + cp1, b1p + koff);
            }
            asm volatile("cp.async.commit_group;\n");
        }

        const uint32_t sA = baseA + (uint32_t)(t % GSTAGES)*8192u;
        const uint32_t sB = baseB + (uint32_t)(t % GSTAGES)*8192u;

        for (int ks = 0; ks < 2; ++ks) {
            uint32_t af[2][4];
            for (int mi = 0; mi < 2; ++mi) {
                asm volatile("ldmatrix.sync.aligned.m8n8.x4.shared.b16 {%0,%1,%2,%3}, [%4];\n"
                    : "=r"(af[mi][0]), "=r"(af[mi][1]), "=r"(af[mi][2]), "=r"(af[mi][3])
                    : "r"(sA + aoff[mi][ks]));
            }
            uint32_t bf[4][4];
            for (int nb4 = 0; nb4 < 4; ++nb4) {
                asm volatile("ldmatrix.sync.aligned.m8n8.x4.shared.b16 {%0,%1,%2,%3}, [%4];\n"
                    : "=r"(bf[nb4][0]), "=r"(bf[nb4][1]), "=r"(bf[nb4][2]), "=r"(bf[nb4][3])
                    : "r"(sB + boff[nb4][ks]));
            }
            for (int ni = 0; ni < 8; ++ni) {
                const int nb4 = ni >> 1;
                const int h   = ni & 1;
                uint32_t b0 = bf[nb4][h*2];
                uint32_t b1 = bf[nb4][h*2+1];
                mma_bf16(acc[0][ni], af[0], b0, b1);
                mma_bf16(acc[1][ni], af[1], b0, b1);
            }
        }
    }

    for (int mi = 0; mi < 2; ++mi) {
        const int r0 = mBase + wm*32 + mi*16 + g;
        for (int ni = 0; ni < 8; ++ni) {
            const int c0 = nBase + wn*64 + ni*8 + 2*tq;
            epi_store<N,EPI>(p, r0,   c0, acc[mi][ni][0], acc[mi][ni][1], Ttot);
            epi_store<N,EPI>(p, r0+8, c0, acc[mi][ni][2], acc[mi][ni][3], Ttot);
        }
    }
}

// ---- merged weight transposes (two launches) -------------------------------
struct WT8 {
    const float* W[8];
    __nv_bfloat16* O[8];
    int K[8];
    int N[8];
    int tileStart[9];
};

__global__ void k_wt_all(WT8 w, int tileOffset)
{
    __shared__ float t[32][33];
    int tile = blockIdx.x + tileOffset;
    int wi = 0;
    while (tile >= w.tileStart[wi+1]) ++wi;
    int local = tile - w.tileStart[wi];
    const int K = w.K[wi];
    const int N = w.N[wi];
    const int tilesX = N >> 5;
    const int k0 = (local / tilesX) << 5;
    const int n0 = (local % tilesX) << 5;
    const float* W = w.W[wi];
    __nv_bfloat16* O = w.O[wi];
    const int tx = threadIdx.x;
    const int ty = threadIdx.y;
    for (int i = ty; i < 32; i += 8)
        t[i][tx] = W[(size_t)(k0+i)*N + n0 + tx];
    __syncthreads();
    for (int i = ty; i < 32; i += 8)
        O[(size_t)(n0+i)*K + k0 + tx] = __float2bfloat16(t[tx][i]);
}

// ============================================================================
__device__ __forceinline__ void ln_regs(float* v, const float* g, const float* b, int lane)
{
    float s = 0.f;
    for (int i = 0; i < 8; ++i) s += v[i];
    for (int o = 16; o; o >>= 1) s += __shfl_xor_sync(0xffffffffu, s, o);
    const float m = s * (1.f/256.f);
    float var = 0.f;
    for (int i = 0; i < 8; ++i) { float d = v[i]-m; var = fmaf(d,d,var); }
    for (int o = 16; o; o >>= 1) var += __shfl_xor_sync(0xffffffffu, var, o);
    const float r = rsqrtf(var*(1.f/256.f) + 1e-5f);
    for (int i = 0; i < 8; ++i) {
        int c = lane + 32*i;
        v[i] = (v[i]-m)*r*__ldg(g+c) + __ldg(b+c);
    }
}

__device__ __forceinline__ void build_ahat(float* ah, int tid, int nthr)
{
    for (int t = tid; t < 289; t += nthr) {
        int i = t/17;
        int j = t - i*17;
        ah[t] = ((c_adj[i]>>j)&1) ? rsqrtf(c_deg[i]*c_deg[j]) : 0.f;
    }
}

__global__ void __launch_bounds__(256) k_pre(const float* x, const float* g, const float* bv)
{
    __shared__ float cur[17*256];
    __shared__ float ah[289];
    const int b = blockIdx.x;
    const int tid = threadIdx.x;
    const int w = tid >> 5, lane = tid & 31;
    build_ahat(ah, tid, 256);
    for (int l = w; l < 17; l += 8) {
        float v[8];
        const float* row = x + (size_t)b*4352 + l*256;
        for (int i = 0; i < 8; ++i) v[i] = row[lane + 32*i];
        ln_regs(v, g, bv, lane);
        for (int i = 0; i < 8; ++i) cur[l*256 + lane + 32*i] = v[i];
    }
    __syncthreads();
    const int d = tid;
    float v[17];
    for (int j = 0; j < 17; ++j) v[j] = cur[j*256 + d];
    for (int i = 0; i < 17; ++i) {
        float a = 0.f;
        for (int j = 0; j < 17; ++j) a = fmaf(ah[i*17+j], v[j], a);
        g_bufD[((size_t)b*17 + i)*256 + d] = __float2bfloat16(a);
    }
}

__global__ void __launch_bounds__(256) k_mid1()
{
    __shared__ float ah[289];
    const int b = blockIdx.x;
    const int tid = threadIdx.x;
    build_ahat(ah, tid, 256);
    __syncthreads();
    const uint32_t* src = reinterpret_cast<const uint32_t*>(g_bufC + (size_t)b*8704);
    uint32_t* dst = reinterpret_cast<uint32_t*>(g_bufB + (size_t)b*8704);
    float2 v[17];
    for (int j = 0; j < 17; ++j) {
        uint32_t u = __ldg(src + j*256 + tid);
        v[j] = __bfloat1622float2(*reinterpret_cast<__nv_bfloat162*>(&u));
    }
    for (int i = 0; i < 17; ++i) {
        float a0 = 0.f, a1 = 0.f;
        for (int j = 0; j < 17; ++j) {
            const float av = ah[i*17+j];
            a0 = fmaf(av, v[j].x, a0);
            a1 = fmaf(av, v[j].y, a1);
        }
        __nv_bfloat162 r = __floats2bfloat162_rn(a0, a1);
        dst[i*256 + tid] = *reinterpret_cast<uint32_t*>(&r);
    }
}

__global__ void __launch_bounds__(256) k_mid2(const float* bp, const float* g, const float* bv)
{
    const int b = blockIdx.x;
    const int tid = threadIdx.x;
    const int w = tid >> 5, lane = tid & 31;
    for (int l = w; l < 17; l += 8) {
        float v[8];
        const float* row = g_res1 + (size_t)b*4352 + c_hop[l]*256;
        const float* bpe = bp + c_bpe[l]*256;
        for (int i = 0; i < 8; ++i) v[i] = row[lane + 32*i] + __ldg(bpe + lane + 32*i);
        ln_regs(v, g, bv, lane);
        __nv_bfloat16* out = g_bufD + ((size_t)b*17 + l)*256;
        for (int i = 0; i < 8; ++i) out[lane + 32*i] = __float2bfloat16(v[i]);
    }
}

__global__ void __launch_bounds__(256) k_mid3(const float* g, const float* bv)
{
    const int b = blockIdx.x;
    const int tid = threadIdx.x;
    const int w = tid >> 5, lane = tid & 31;
    for (int l = w; l < 17; l += 8) {
        float v[8];
        const float* r1 = g_res1 + (size_t)b*4352 + l*256;
        const float* xo = g_tmpf + (size_t)b*4352 + c_graph[l]*256;
        float* r2 = g_res2 + (size_t)b*4352 + l*256;
        for (int i = 0; i < 8; ++i) {
            v[i] = 2.f*r1[lane + 32*i] + xo[lane + 32*i];
            r2[lane + 32*i] = v[i];
        }
        ln_regs(v, g, bv, lane);
        __nv_bfloat16* out = g_bufD + ((size_t)b*17 + l)*256;
        for (int i = 0; i < 8; ++i) out[lane + 32*i] = __float2bfloat16(v[i]);
    }
}

__global__ void __launch_bounds__(256) k_ln2(const float* g, const float* bv)
{
    const int b = blockIdx.x;
    const int tid = threadIdx.x;
    const int w = tid >> 5, lane = tid & 31;
    for (int l = w; l < 17; l += 8) {
        float v[8];
        const float* row = g_x1 + (size_t)b*4352 + l*256;
        for (int i = 0; i < 8; ++i) v[i] = row[lane + 32*i];
        ln_regs(v, g, bv, lane);
        __nv_bfloat16* out = g_bufD + ((size_t)b*17 + l)*256;
        for (int i = 0; i < 8; ++i) out[lane + 32*i] = __float2bfloat16(v[i]);
    }
}

#define SCAN_SMEM_FLOATS (8704 + 408)

__global__ void __launch_bounds__(512) k_scan(const float* x_proj_w,
                                              const float* dt_proj_w,
                                              const float* dt_proj_b,
                                              const float* A_log,
                                              const float* Dpv)
{
    extern __shared__ float sm[];
    float* xm  = sm;
    float* dbl = sm + 8704;
    const int b = blockIdx.x;
    const int tid = threadIdx.x;
    for (int i = tid; i < 4352; i += 512) {
        int l = i >> 8;
        int wq = i & 255;
        const uint32_t* row = reinterpret_cast<const uint32_t*>(g_bufA + ((size_t)b*17 + l)*1024);
        uint32_t u = __ldg(row + wq);
        float2 f = __bfloat1622float2(*reinterpret_cast<__nv_bfloat162*>(&u));
        xm[l*512 + 2*wq]   = f.x;
        xm[l*512 + 2*wq+1] = f.y;
    }
    __syncthreads();
    if (tid < 408) {
        int l = tid/24;
        int n = tid - l*24;
        const float* xr = xm + l*512;
        float a = 0.f;
#pragma unroll 8
        for (int k = 0; k < 512; ++k) a = fmaf(xr[k], __ldg(x_proj_w + k*24 + n), a);
        dbl[tid] = a;
    }
    __syncthreads();
    const int d = tid;
    float negA[4];
    float h[4] = {0.f,0.f,0.f,0.f};
    float wdt[16];
    for (int s = 0; s < 4; ++s) negA[s] = -expf(__ldg(A_log + d*4 + s));
    for (int r = 0; r < 16; ++r) wdt[r] = __ldg(dt_proj_w + r*512 + d);
    const float dpb = __ldg(dt_proj_b + d);
    const float Dp  = __ldg(Dpv + d);
    for (int l = 0; l < 17; ++l) {
        const float* dl = dbl + l*24;
        float t0 = dpb;
        for (int r = 0; r < 16; ++r) t0 = fmaf(dl[r], wdt[r], t0);
        const float dt = softplus_f(t0);
        const float xv = xm[l*512 + d];
        float y = 0.f;
        for (int s = 0; s < 4; ++s) {
            const float Bv = dl[16+s];
            const float Cv = dl[20+s];
            h[s] = fmaf(expf(dt*negA[s]), h[s], dt*Bv*xv);
            y = fmaf(h[s], Cv, y);
        }
        y = fmaf(Dp, xv, y);
        const float z = __bfloat162float(g_bufA[((size_t)b*17 + l)*1024 + 512 + d]);
        g_bufC[((size_t)b*17 + l)*512 + d] = __float2bfloat16(y * z);
    }
}

__global__ void __launch_bounds__(512) k_attn()
{
    extern __shared__ float s[];
    const int b = blockIdx.x;
    const int tid = threadIdx.x;
    const uint32_t* qp = reinterpret_cast<const uint32_t*>(g_bufB + (size_t)b*13056);
    for (int i = tid; i < 6528; i += 512) {
        uint32_t u = __ldg(qp + i);
        float2 f = __bfloat1622float2(*reinterpret_cast<__nv_bfloat162*>(&u));
        s[2*i]   = f.x;
        s[2*i+1] = f.y;
    }
    __syncthreads();
    const int lane = tid & 31;
    const int w = tid >> 5;
    const float scale = 0.17677669529663687f;
    for (int task = w; task < 136; task += 16) {
        const int q = task >> 3;
        const int hh = task & 7;
        const int off = hh*32 + lane;
        const float qj = s[q*768 + off];
        float sc[17];
        float mx = -1e30f;
        for (int k = 0; k < 17; ++k) {
            float pv = qj * s[k*768 + 256 + off];
            for (int o = 16; o; o >>= 1) pv += __shfl_xor_sync(0xffffffffu, pv, o);
            pv *= scale;
            sc[k] = pv;
            mx = fmaxf(mx, pv);
        }
        float sum = 0.f;
        for (int k = 0; k < 17; ++k) { sc[k] = expf(sc[k]-mx); sum += sc[k]; }
        const float inv = 1.f/sum;
        float acc = 0.f;
        for (int k = 0; k < 17; ++k)
            acc = fmaf(sc[k]*inv, s[k*768 + 512 + off], acc);
        g_bufD[((size_t)b*17 + q)*256 + off] = __float2bfloat16(acc);
    }
}

// ============================================================================
extern "C" void kernel_launch(void* const* d_in, const int* in_sizes, int n_in,
                              void* d_out, int out_size)
{
    const float *x          = (const float*)d_in[0];
    const float *gcn_ln_g   = (const float*)d_in[1];
    const float *gcn_ln_b   = (const float*)d_in[2];
    const float *gcn_w1     = (const float*)d_in[3];
    const float *gcn_b1     = (const float*)d_in[4];
    const float *gcn_w2     = (const float*)d_in[5];
    const float *gcn_b2     = (const float*)d_in[6];
    const float *bp         = (const float*)d_in[7];
    const float *ssm_ln_g   = (const float*)d_in[8];
    const float *ssm_ln_b   = (const float*)d_in[9];
    const float *in_proj_w  = (const float*)d_in[10];
    const float *conv_w     = (const float*)d_in[11];
    const float *conv_b     = (const float*)d_in[12];
    const float *x_proj_w   = (const float*)d_in[13];
    const float *dt_proj_w  = (const float*)d_in[14];
    const float *dt_proj_b  = (const float*)d_in[15];
    const float *A_log      = (const float*)d_in[16];
    const float *Dp         = (const float*)d_in[17];
    const float *out_proj_w = (const float*)d_in[18];
    const float *ln1_g      = (const float*)d_in[19];
    const float *ln1_b      = (const float*)d_in[20];
    const float *qkv_w      = (const float*)d_in[21];
    const float *attn_proj_w= (const float*)d_in[22];
    const float *attn_proj_b= (const float*)d_in[23];
    const float *ln2_g      = (const float*)d_in[24];
    const float *ln2_b      = (const float*)d_in[25];
    const float *mlp_w1     = (const float*)d_in[26];
    const float *mlp_b1     = (const float*)d_in[27];
    const float *mlp_w2     = (const float*)d_in[28];
    const float *mlp_b2     = (const float*)d_in[29];
    float* outp             = (float*)d_out;

    const int nb   = in_sizes[0] / 4352;
    const int Ttot = nb * 17;
    const int mT   = (Ttot + 127) / 128;

    __nv_bfloat16 *bufA = 0, *bufB = 0, *bufC = 0, *bufD = 0, *wt = 0;
    float *res1 = 0, *res2 = 0, *x1 = 0, *tmpf = 0;
    cudaGetSymbolAddress((void**)&bufA, g_bufA);
    cudaGetSymbolAddress((void**)&bufB, g_bufB);
    cudaGetSymbolAddress((void**)&bufC, g_bufC);
    cudaGetSymbolAddress((void**)&bufD, g_bufD);
    cudaGetSymbolAddress((void**)&res1, g_res1);
    cudaGetSymbolAddress((void**)&res2, g_res2);
    cudaGetSymbolAddress((void**)&x1,   g_x1);
    cudaGetSymbolAddress((void**)&tmpf, g_tmpf);
    cudaGetSymbolAddress((void**)&wt,   g_wt);

    __nv_bfloat16* wt_gcn1 = wt;
    __nv_bfloat16* wt_gcn2 = wt + 131072;
    __nv_bfloat16* wt_inp  = wt + 262144;
    __nv_bfloat16* wt_outp = wt + 524288;
    __nv_bfloat16* wt_qkv  = wt + 655360;
    __nv_bfloat16* wt_attn = wt + 851968;
    __nv_bfloat16* wt_mlp1 = wt + 917504;
    __nv_bfloat16* wt_mlp2 = wt + 1179648;

    const int scan_smem = SCAN_SMEM_FLOATS * 4;
    cudaFuncSetAttribute(k_scan, cudaFuncAttributeMaxDynamicSharedMemorySize, scan_smem);
    cudaFuncSetAttribute(k_attn, cudaFuncAttributeMaxDynamicSharedMemorySize, 13056*4);
    cudaFuncSetAttribute(gemm_tc<256,512,1>,  cudaFuncAttributeMaxDynamicSharedMemorySize, GSMEM);
    cudaFuncSetAttribute(gemm_tc<512,256,2>,  cudaFuncAttributeMaxDynamicSharedMemorySize, GSMEM);
    cudaFuncSetAttribute(gemm_tc<256,1024,4>, cudaFuncAttributeMaxDynamicSharedMemorySize, GSMEM);
    cudaFuncSetAttribute(gemm_tc<512,256,3>,  cudaFuncAttributeMaxDynamicSharedMemorySize, GSMEM);
    cudaFuncSetAttribute(gemm_tc<256,768,0>,  cudaFuncAttributeMaxDynamicSharedMemorySize, GSMEM);
    cudaFuncSetAttribute(gemm_tc<256,256,2>,  cudaFuncAttributeMaxDynamicSharedMemorySize, GSMEM);
    cudaFuncSetAttribute(gemm_tc<256,1024,1>, cudaFuncAttributeMaxDynamicSharedMemorySize, GSMEM);
    cudaFuncSetAttribute(gemm_tc<1024,256,5>, cudaFuncAttributeMaxDynamicSharedMemorySize, GSMEM);

    WT8 w;
    w.W[0]=gcn_w1;      w.O[0]=wt_gcn1; w.K[0]=256;  w.N[0]=512;
    w.W[1]=gcn_w2;      w.O[1]=wt_gcn2; w.K[1]=512;  w.N[1]=256;
    w.W[2]=in_proj_w;   w.O[2]=wt_inp;  w.K[2]=256;  w.N[2]=1024;
    w.W[3]=out_proj_w;  w.O[3]=wt_outp; w.K[3]=512;  w.N[3]=256;
    w.W[4]=qkv_w;       w.O[4]=wt_qkv;  w.K[4]=256;  w.N[4]=768;
    w.W[5]=attn_proj_w; w.O[5]=wt_attn; w.K[5]=256;  w.N[5]=256;
    w.W[6]=mlp_w1;      w.O[6]=wt_mlp1; w.K[6]=256;  w.N[6]=1024;
    w.W[7]=mlp_w2;      w.O[7]=wt_mlp2; w.K[7]=1024; w.N[7]=256;
    {
        int acc = 0;
        for (int i = 0; i < 8; ++i) {
            w.tileStart[i] = acc;
            acc += (w.K[i]/32)*(w.N[i]/32);
        }
        w.tileStart[8] = acc;
        dim3 tb(32, 8);
        const int half = acc / 2;
        k_wt_all<<<half, tb>>>(w, 0);
        k_wt_all<<<acc - half, tb>>>(w, half);
    }

    // Stage A: GCN
    k_pre<<<nb, 256>>>(x, gcn_ln_g, gcn_ln_b);
    GP p1 = { bufD, wt_gcn1, gcn_b1, 0, 0, 0, 0, 0, bufC };
    gemm_tc<256,512,1><<<dim3(4, mT), 256, GSMEM>>>(p1, Ttot);
    k_mid1<<<nb, 256>>>();
    GP p2 = { bufB, wt_gcn2, gcn_b2, x, 0, 0, 0, res1, 0 };
    gemm_tc<512,256,2><<<dim3(2, mT), 256, GSMEM>>>(p2, Ttot);

    // Stage B: SSM
    k_mid2<<<nb, 256>>>(bp, ssm_ln_g, ssm_ln_b);
    GP p3 = { bufD, wt_inp, 0, 0, 0, conv_w, conv_b, 0, bufA };
    gemm_tc<256,1024,4><<<dim3(8, mT), 256, GSMEM>>>(p3, Ttot);
    k_scan<<<nb, 512, scan_smem>>>(x_proj_w, dt_proj_w, dt_proj_b, A_log, Dp);
    GP p4 = { bufC, wt_outp, 0, 0, 0, 0, 0, tmpf, 0 };
    gemm_tc<512,256,3><<<dim3(2, mT), 256, GSMEM>>>(p4, Ttot);
    k_mid3<<<nb, 256>>>(ln1_g, ln1_b);

    // Stage C: attention
    GP p5 = { bufD, wt_qkv, 0, 0, 0, 0, 0, 0, bufB };
    gemm_tc<256,768,0><<<dim3(6, mT), 256, GSMEM>>>(p5, Ttot);
    k_attn<<<nb, 512, 13056*4>>>();
    GP p6 = { bufD, wt_attn, attn_proj_b, res2, 0, 0, 0, x1, 0 };
    gemm_tc<256,256,2><<<dim3(2, mT), 256, GSMEM>>>(p6, Ttot);

    // Stage D: MLP
    k_ln2<<<nb, 256>>>(ln2_g, ln2_b);
    GP p7 = { bufD, wt_mlp1, mlp_b1, 0, 0, 0, 0, 0, bufA };
    gemm_tc<256,1024,1><<<dim3(8, mT), 256, GSMEM>>>(p7, Ttot);
    GP p8 = { bufA, wt_mlp2, mlp_b2, x1, res2, 0, 0, outp, 0 };
    gemm_tc<1024,256,5><<<dim3(2, mT), 256, GSMEM>>>(p8, Ttot);
}

// round 17
// speedup vs baseline: 1.4236x; 1.4236x over previous
#include <cuda_runtime.h>
#include <cuda_bf16.h>
#include <cstdint>
#include <math.h>

#define TMAX 69632

__constant__ int   c_adj[17]  = {0x93,0x7,0xE,0xC,0x31,0x70,0x60,0x181,0x4B80,
                                 0x700,0x600,0x1900,0x3800,0x3000,0xC100,0x1C000,0x18000};
__constant__ float c_deg[17]  = {4,3,3,2,3,3,2,3,5,3,2,3,3,2,3,3,2};
__constant__ int   c_hop[17]  = {0,1,4,7,2,5,8,3,6,9,11,14,10,12,15,13,16};
__constant__ int   c_graph[17]= {0,1,4,7,2,5,8,3,6,9,12,10,13,15,11,14,16};
__constant__ int   c_bpe[17]  = {0,1,2,0,1,2,0,1,2,0,3,4,0,3,4,3,4};

__device__ __nv_bfloat16 g_bufA[(size_t)TMAX*1024];
__device__ __nv_bfloat16 g_bufB[(size_t)TMAX*768];
__device__ __nv_bfloat16 g_bufC[(size_t)TMAX*512];
__device__ __nv_bfloat16 g_bufD[(size_t)TMAX*256];
__device__ float g_res1[(size_t)TMAX*256];
__device__ float g_res2[(size_t)TMAX*256];
__device__ float g_x1  [(size_t)TMAX*256];
__device__ float g_tmpf[(size_t)TMAX*256];
__device__ __nv_bfloat16 g_wt[1441792];

__device__ __forceinline__ float gelu_t(float x) {
    float x3 = x*x*x;
    return 0.5f*x*(1.f + tanhf(0.7978845608028654f*(x + 0.044715f*x3)));
}
__device__ __forceinline__ float silu_f(float x) { return x / (1.f + expf(-x)); }
__device__ __forceinline__ float softplus_f(float x) { return x > 20.f ? x : log1pf(expf(x)); }

struct GP {
    const __nv_bfloat16* A;
    const __nv_bfloat16* Wt;
    const float* bias;
    const float* add1;
    const float* add2;
    const float* cw;
    const float* cb;
    float* outf;
    __nv_bfloat16* outh;
};

__device__ __forceinline__ void mma_bf16(float* d, const uint32_t* a,
                                         uint32_t b0, uint32_t b1)
{
    asm volatile(
        "mma.sync.aligned.m16n8k16.row.col.f32.bf16.bf16.f32 "
        "{%0,%1,%2,%3}, {%4,%5,%6,%7}, {%8,%9}, {%0,%1,%2,%3};\n"
        : "+f"(d[0]), "+f"(d[1]), "+f"(d[2]), "+f"(d[3])
        : "r"(a[0]), "r"(a[1]), "r"(a[2]), "r"(a[3]), "r"(b0), "r"(b1));
}

// swizzled byte offset of 16B chunk (r, c) within a [128][32]bf16 tile
__device__ __forceinline__ uint32_t sw_off(int r, int c)
{
    return (uint32_t)((r*4 + (c ^ ((r>>1)&3))) << 4);
}

__device__ __forceinline__ void cp16(uint32_t smem, const void* gmem)
{
    asm volatile("cp.async.cg.shared.global [%0], [%1], 16;\n" :: "r"(smem), "l"(gmem));
}

// vectorized epilogue: v0 at column c (even), v1 at c+1
template<int N, int EPI>
__device__ __forceinline__ void epi_store(const GP& p, int t, int c,
                                          float v0, float v1, int Ttot)
{
    if (t >= Ttot) return;
    if (EPI == 0) {
        __nv_bfloat162 r = __floats2bfloat162_rn(v0, v1);
        *reinterpret_cast<__nv_bfloat162*>(p.outh + (size_t)t*N + c) = r;
    }
    if (EPI == 1) {
        float2 bb = *reinterpret_cast<const float2*>(p.bias + c);
        v0 = gelu_t(v0 + bb.x);
        v1 = gelu_t(v1 + bb.y);
        __nv_bfloat162 r = __floats2bfloat162_rn(v0, v1);
        *reinterpret_cast<__nv_bfloat162*>(p.outh + (size_t)t*N + c) = r;
    }
    if (EPI == 2) {
        float2 bb = *reinterpret_cast<const float2*>(p.bias + c);
        float2 a1 = *reinterpret_cast<const float2*>(p.add1 + (size_t)t*256 + c);
        float2 o;
        o.x = v0 + bb.x + a1.x;
        o.y = v1 + bb.y + a1.y;
        *reinterpret_cast<float2*>(p.outf + (size_t)t*256 + c) = o;
    }
    if (EPI == 3) {
        float2 o; o.x = v0; o.y = v1;
        *reinterpret_cast<float2*>(p.outf + (size_t)t*256 + c) = o;
    }
    if (EPI == 4) {
        if (c < 512) {
            float2 cw = *reinterpret_cast<const float2*>(p.cw + c);
            float2 cb = *reinterpret_cast<const float2*>(p.cb + c);
            v0 = silu_f(fmaf(v0, cw.x, cb.x));
            v1 = silu_f(fmaf(v1, cw.y, cb.y));
        } else {
            v0 = silu_f(v0);
            v1 = silu_f(v1);
        }
        __nv_bfloat162 r = __floats2bfloat162_rn(v0, v1);
        *reinterpret_cast<__nv_bfloat162*>(p.outh + (size_t)t*1024 + c) = r;
    }
    if (EPI == 5) {
        float2 bb = *reinterpret_cast<const float2*>(p.bias + c);
        float2 a1 = *reinterpret_cast<const float2*>(p.add1 + (size_t)t*256 + c);
        float2 a2 = *reinterpret_cast<const float2*>(p.add2 + (size_t)t*256 + c);
        float2 o;
        o.x = v0 + bb.x + a1.x + a2.x;
        o.y = v1 + bb.y + a1.y + a2.y;
        *reinterpret_cast<float2*>(p.outf + (size_t)t*256 + c) = o;
    }
}

// ---- GEMM: CTA tile 128x128, 8 warps (4m x 2n), warp tile 32x64 (R15) ------
template<int K, int N, int EPI>
__global__ void __launch_bounds__(256, 2) gemm_tc(GP p, int Ttot)
{
    __shared__ __nv_bfloat16 As[3][128*32];
    __shared__ __nv_bfloat16 Bs[3][128*32];
    const int tid  = threadIdx.x;
    const int lane = tid & 31;
    const int wid  = tid >> 5;
    const int wm = wid & 3;
    const int wn = wid >> 2;
    const int mBase = blockIdx.y * 128;
    const int nBase = blockIdx.x * 128;
    const int g  = lane >> 2;
    const int tq = lane & 3;
    constexpr int NT_TILES = K / 32;

    const uint32_t baseA = (uint32_t)__cvta_generic_to_shared(&As[0][0]);
    const uint32_t baseB = (uint32_t)__cvta_generic_to_shared(&Bs[0][0]);

    const int r0s = tid >> 2,        c0s = tid & 3;
    const int r1s = (tid+256) >> 2,  c1s = tid & 3;
    int gr0 = mBase + r0s; if (gr0 >= Ttot) gr0 = Ttot - 1;
    int gr1 = mBase + r1s; if (gr1 >= Ttot) gr1 = Ttot - 1;
    const __nv_bfloat16* a0p = p.A  + (size_t)gr0*K          + c0s*8;
    const __nv_bfloat16* a1p = p.A  + (size_t)gr1*K          + c1s*8;
    const __nv_bfloat16* b0p = p.Wt + (size_t)(nBase+r0s)*K  + c0s*8;
    const __nv_bfloat16* b1p = p.Wt + (size_t)(nBase+r1s)*K  + c1s*8;

    // hoisted swizzled offsets (stage-relative)
    const uint32_t cp0 = sw_off(r0s, c0s);
    const uint32_t cp1 = sw_off(r1s, c1s);
    uint32_t aoff[2][2];   // [mi][ks]
    for (int mi = 0; mi < 2; ++mi)
        for (int ks = 0; ks < 2; ++ks) {
            const int rr = wm*32 + mi*16 + (lane & 15);
            const int cc = 2*ks + (lane >> 4);
            aoff[mi][ks] = sw_off(rr, cc);
        }
    uint32_t boff[4][2];   // [nb4][ks]
    for (int nb4 = 0; nb4 < 4; ++nb4)
        for (int ks = 0; ks < 2; ++ks) {
            const int midx = lane >> 3;
            const int rr = wn*64 + nb4*16 + (midx>>1)*8 + (lane & 7);
            const int cc = 2*ks + (midx & 1);
            boff[nb4][ks] = sw_off(rr, cc);
        }

    float acc[2][8][4];
    for (int a = 0; a < 2; ++a)
        for (int b = 0; b < 8; ++b)
            for (int c = 0; c < 4; ++c)
                acc[a][b][c] = 0.f;

    // prologue: issue tiles 0 and 1
    for (int t = 0; t < 2; ++t) {
        if (t < NT_TILES) {
            const int koff = t*32;
            const uint32_t sA = baseA + (uint32_t)(t % 3)*8192u;
            const uint32_t sB = baseB + (uint32_t)(t % 3)*8192u;
            cp16(sA + cp0, a0p + koff);
            cp16(sA + cp1, a1p + koff);
            cp16(sB + cp0, b0p + koff);
            cp16(sB + cp1, b1p + koff);
        }
        asm volatile("cp.async.commit_group;\n");
    }

#pragma unroll
    for (int t = 0; t < NT_TILES; ++t) {
        // RAW: pending {t, t+1}; wait to <=1 pending => tile t landed.
        asm volatile("cp.async.wait_group 1;\n");
        __syncthreads();
        // WAR: stage (t+2)%3's readers ran in iteration t-1, before this barrier.
        {
            const int tn = t + 2;
            if (tn < NT_TILES) {
                const int koff = tn*32;
                const uint32_t sA = baseA + (uint32_t)(tn % 3)*8192u;
                const uint32_t sB = baseB + (uint32_t)(tn % 3)*8192u;
                cp16(sA + cp0, a0p + koff);
                cp16(sA + cp1, a1p + koff);
                cp16(sB + cp0, b0p + koff);
                cp16(sB + cp1, b1p + koff);
            }
            asm volatile("cp.async.commit_group;\n");
        }

        const uint32_t sA = baseA + (uint32_t)(t % 3)*8192u;
        const uint32_t sB = baseB + (uint32_t)(t % 3)*8192u;

        for (int ks = 0; ks < 2; ++ks) {
            uint32_t af[2][4];
            for (int mi = 0; mi < 2; ++mi) {
                asm volatile("ldmatrix.sync.aligned.m8n8.x4.shared.b16 {%0,%1,%2,%3}, [%4];\n"
                    : "=r"(af[mi][0]), "=r"(af[mi][1]), "=r"(af[mi][2]), "=r"(af[mi][3])
                    : "r"(sA + aoff[mi][ks]));
            }
            uint32_t bf[4][4];
            for (int nb4 = 0; nb4 < 4; ++nb4) {
                asm volatile("ldmatrix.sync.aligned.m8n8.x4.shared.b16 {%0,%1,%2,%3}, [%4];\n"
                    : "=r"(bf[nb4][0]), "=r"(bf[nb4][1]), "=r"(bf[nb4][2]), "=r"(bf[nb4][3])
                    : "r"(sB + boff[nb4][ks]));
            }
            for (int ni = 0; ni < 8; ++ni) {
                const int nb4 = ni >> 1;
                const int h   = ni & 1;
                uint32_t b0 = bf[nb4][h*2];
                uint32_t b1 = bf[nb4][h*2+1];
                mma_bf16(acc[0][ni], af[0], b0, b1);
                mma_bf16(acc[1][ni], af[1], b0, b1);
            }
        }
    }

    for (int mi = 0; mi < 2; ++mi) {
        const int r0 = mBase + wm*32 + mi*16 + g;
        for (int ni = 0; ni < 8; ++ni) {
            const int c0 = nBase + wn*64 + ni*8 + 2*tq;
            epi_store<N,EPI>(p, r0,   c0, acc[mi][ni][0], acc[mi][ni][1], Ttot);
            epi_store<N,EPI>(p, r0+8, c0, acc[mi][ni][2], acc[mi][ni][3], Ttot);
        }
    }
}

// ---- merged weight transposes (two launches) -------------------------------
struct WT8 {
    const float* W[8];
    __nv_bfloat16* O[8];
    int K[8];
    int N[8];
    int tileStart[9];
};

__global__ void k_wt_all(WT8 w, int tileOffset)
{
    __shared__ float t[32][33];
    int tile = blockIdx.x + tileOffset;
    int wi = 0;
    while (tile >= w.tileStart[wi+1]) ++wi;
    int local = tile - w.tileStart[wi];
    const int K = w.K[wi];
    const int N = w.N[wi];
    const int tilesX = N >> 5;
    const int k0 = (local / tilesX) << 5;
    const int n0 = (local % tilesX) << 5;
    const float* W = w.W[wi];
    __nv_bfloat16* O = w.O[wi];
    const int tx = threadIdx.x;
    const int ty = threadIdx.y;
    for (int i = ty; i < 32; i += 8)
        t[i][tx] = W[(size_t)(k0+i)*N + n0 + tx];
    __syncthreads();
    for (int i = ty; i < 32; i += 8)
        O[(size_t)(n0+i)*K + k0 + tx] = __float2bfloat16(t[tx][i]);
}

// ============================================================================
__device__ __forceinline__ void ln_regs(float* v, const float* g, const float* b, int lane)
{
    float s = 0.f;
    for (int i = 0; i < 8; ++i) s += v[i];
    for (int o = 16; o; o >>= 1) s += __shfl_xor_sync(0xffffffffu, s, o);
    const float m = s * (1.f/256.f);
    float var = 0.f;
    for (int i = 0; i < 8; ++i) { float d = v[i]-m; var = fmaf(d,d,var); }
    for (int o = 16; o; o >>= 1) var += __shfl_xor_sync(0xffffffffu, var, o);
    const float r = rsqrtf(var*(1.f/256.f) + 1e-5f);
    for (int i = 0; i < 8; ++i) {
        int c = lane + 32*i;
        v[i] = (v[i]-m)*r*__ldg(g+c) + __ldg(b+c);
    }
}

__device__ __forceinline__ void build_ahat(float* ah, int tid, int nthr)
{
    for (int t = tid; t < 289; t += nthr) {
        int i = t/17;
        int j = t - i*17;
        ah[t] = ((c_adj[i]>>j)&1) ? rsqrtf(c_deg[i]*c_deg[j]) : 0.f;
    }
}

__global__ void __launch_bounds__(256) k_pre(const float* x, const float* g, const float* bv)
{
    __shared__ float cur[17*256];
    __shared__ float ah[289];
    const int b = blockIdx.x;
    const int tid = threadIdx.x;
    const int w = tid >> 5, lane = tid & 31;
    build_ahat(ah, tid, 256);
    for (int l = w; l < 17; l += 8) {
        float v[8];
        const float* row = x + (size_t)b*4352 + l*256;
        for (int i = 0; i < 8; ++i) v[i] = row[lane + 32*i];
        ln_regs(v, g, bv, lane);
        for (int i = 0; i < 8; ++i) cur[l*256 + lane + 32*i] = v[i];
    }
    __syncthreads();
    const int d = tid;
    float v[17];
    for (int j = 0; j < 17; ++j) v[j] = cur[j*256 + d];
    for (int i = 0; i < 17; ++i) {
        float a = 0.f;
        for (int j = 0; j < 17; ++j) a = fmaf(ah[i*17+j], v[j], a);
        g_bufD[((size_t)b*17 + i)*256 + d] = __float2bfloat16(a);
    }
}

__global__ void __launch_bounds__(256) k_mid1()
{
    __shared__ float ah[289];
    const int b = blockIdx.x;
    const int tid = threadIdx.x;
    build_ahat(ah, tid, 256);
    __syncthreads();
    const uint32_t* src = reinterpret_cast<const uint32_t*>(g_bufC + (size_t)b*8704);
    uint32_t* dst = reinterpret_cast<uint32_t*>(g_bufB + (size_t)b*8704);
    float2 v[17];
    for (int j = 0; j < 17; ++j) {
        uint32_t u = __ldg(src + j*256 + tid);
        v[j] = __bfloat1622float2(*reinterpret_cast<__nv_bfloat162*>(&u));
    }
    for (int i = 0; i < 17; ++i) {
        float a0 = 0.f, a1 = 0.f;
        for (int j = 0; j < 17; ++j) {
            const float av = ah[i*17+j];
            a0 = fmaf(av, v[j].x, a0);
            a1 = fmaf(av, v[j].y, a1);
        }
        __nv_bfloat162 r = __floats2bfloat162_rn(a0, a1);
        dst[i*256 + tid] = *reinterpret_cast<uint32_t*>(&r);
    }
}

__global__ void __launch_bounds__(256) k_mid2(const float* bp, const float* g, const float* bv)
{
    const int b = blockIdx.x;
    const int tid = threadIdx.x;
    const int w = tid >> 5, lane = tid & 31;
    for (int l = w; l < 17; l += 8) {
        float v[8];
        const float* row = g_res1 + (size_t)b*4352 + c_hop[l]*256;
        const float* bpe = bp + c_bpe[l]*256;
        for (int i = 0; i < 8; ++i) v[i] = row[lane + 32*i] + __ldg(bpe + lane + 32*i);
        ln_regs(v, g, bv, lane);
        __nv_bfloat16* out = g_bufD + ((size_t)b*17 + l)*256;
        for (int i = 0; i < 8; ++i) out[lane + 32*i] = __float2bfloat16(v[i]);
    }
}

__global__ void __launch_bounds__(256) k_mid3(const float* g, const float* bv)
{
    const int b = blockIdx.x;
    const int tid = threadIdx.x;
    const int w = tid >> 5, lane = tid & 31;
    for (int l = w; l < 17; l += 8) {
        float v[8];
        const float* r1 = g_res1 + (size_t)b*4352 + l*256;
        const float* xo = g_tmpf + (size_t)b*4352 + c_graph[l]*256;
        float* r2 = g_res2 + (size_t)b*4352 + l*256;
        for (int i = 0; i < 8; ++i) {
            v[i] = 2.f*r1[lane + 32*i] + xo[lane + 32*i];
            r2[lane + 32*i] = v[i];
        }
        ln_regs(v, g, bv, lane);
        __nv_bfloat16* out = g_bufD + ((size_t)b*17 + l)*256;
        for (int i = 0; i < 8; ++i) out[lane + 32*i] = __float2bfloat16(v[i]);
    }
}

__global__ void __launch_bounds__(256) k_ln2(const float* g, const float* bv)
{
    const int b = blockIdx.x;
    const int tid = threadIdx.x;
    const int w = tid >> 5, lane = tid & 31;
    for (int l = w; l < 17; l += 8) {
        float v[8];
        const float* row = g_x1 + (size_t)b*4352 + l*256;
        for (int i = 0; i < 8; ++i) v[i] = row[lane + 32*i];
        ln_regs(v, g, bv, lane);
        __nv_bfloat16* out = g_bufD + ((size_t)b*17 + l)*256;
        for (int i = 0; i < 8; ++i) out[lane + 32*i] = __float2bfloat16(v[i]);
    }
}

#define SCAN_SMEM_FLOATS (8704 + 408)

__global__ void __launch_bounds__(512) k_scan(const float* x_proj_w,
                                              const float* dt_proj_w,
                                              const float* dt_proj_b,
                                              const float* A_log,
                                              const float* Dpv)
{
    extern __shared__ float sm[];
    float* xm  = sm;
    float* dbl = sm + 8704;
    const int b = blockIdx.x;
    const int tid = threadIdx.x;
    for (int i = tid; i < 4352; i += 512) {
        int l = i >> 8;
        int wq = i & 255;
        const uint32_t* row = reinterpret_cast<const uint32_t*>(g_bufA + ((size_t)b*17 + l)*1024);
        uint32_t u = __ldg(row + wq);
        float2 f = __bfloat1622float2(*reinterpret_cast<__nv_bfloat162*>(&u));
        xm[l*512 + 2*wq]   = f.x;
        xm[l*512 + 2*wq+1] = f.y;
    }
    __syncthreads();
    if (tid < 408) {
        int l = tid/24;
        int n = tid - l*24;
        const float* xr = xm + l*512;
        float a = 0.f;
#pragma unroll 8
        for (int k = 0; k < 512; ++k) a = fmaf(xr[k], __ldg(x_proj_w + k*24 + n), a);
        dbl[tid] = a;
    }
    __syncthreads();
    const int d = tid;
    float negA[4];
    float h[4] = {0.f,0.f,0.f,0.f};
    float wdt[16];
    for (int s = 0; s < 4; ++s) negA[s] = -expf(__ldg(A_log + d*4 + s));
    for (int r = 0; r < 16; ++r) wdt[r] = __ldg(dt_proj_w + r*512 + d);
    const float dpb = __ldg(dt_proj_b + d);
    const float Dp  = __ldg(Dpv + d);
    for (int l = 0; l < 17; ++l) {
        const float* dl = dbl + l*24;
        float t0 = dpb;
        for (int r = 0; r < 16; ++r) t0 = fmaf(dl[r], wdt[r], t0);
        const float dt = softplus_f(t0);
        const float xv = xm[l*512 + d];
        float y = 0.f;
        for (int s = 0; s < 4; ++s) {
            const float Bv = dl[16+s];
            const float Cv = dl[20+s];
            h[s] = fmaf(expf(dt*negA[s]), h[s], dt*Bv*xv);
            y = fmaf(h[s], Cv, y);
        }
        y = fmaf(Dp, xv, y);
        const float z = __bfloat162float(g_bufA[((size_t)b*17 + l)*1024 + 512 + d]);
        g_bufC[((size_t)b*17 + l)*512 + d] = __float2bfloat16(y * z);
    }
}

__global__ void __launch_bounds__(512) k_attn()
{
    extern __shared__ float s[];
    const int b = blockIdx.x;
    const int tid = threadIdx.x;
    const uint32_t* qp = reinterpret_cast<const uint32_t*>(g_bufB + (size_t)b*13056);
    for (int i = tid; i < 6528; i += 512) {
        uint32_t u = __ldg(qp + i);
        float2 f = __bfloat1622float2(*reinterpret_cast<__nv_bfloat162*>(&u));
        s[2*i]   = f.x;
        s[2*i+1] = f.y;
    }
    __syncthreads();
    const int lane = tid & 31;
    const int w = tid >> 5;
    const float scale = 0.17677669529663687f;
    for (int task = w; task < 136; task += 16) {
        const int q = task >> 3;
        const int hh = task & 7;
        const int off = hh*32 + lane;
        const float qj = s[q*768 + off];
        float sc[17];
        float mx = -1e30f;
        for (int k = 0; k < 17; ++k) {
            float pv = qj * s[k*768 + 256 + off];
            for (int o = 16; o; o >>= 1) pv += __shfl_xor_sync(0xffffffffu, pv, o);
            pv *= scale;
            sc[k] = pv;
            mx = fmaxf(mx, pv);
        }
        float sum = 0.f;
        for (int k = 0; k < 17; ++k) { sc[k] = expf(sc[k]-mx); sum += sc[k]; }
        const float inv = 1.f/sum;
        float acc = 0.f;
        for (int k = 0; k < 17; ++k)
            acc = fmaf(sc[k]*inv, s[k*768 + 512 + off], acc);
        g_bufD[((size_t)b*17 + q)*256 + off] = __float2bfloat16(acc);
    }
}

// ============================================================================
extern "C" void kernel_launch(void* const* d_in, const int* in_sizes, int n_in,
                              void* d_out, int out_size)
{
    const float *x          = (const float*)d_in[0];
    const float *gcn_ln_g   = (const float*)d_in[1];
    const float *gcn_ln_b   = (const float*)d_in[2];
    const float *gcn_w1     = (const float*)d_in[3];
    const float *gcn_b1     = (const float*)d_in[4];
    const float *gcn_w2     = (const float*)d_in[5];
    const float *gcn_b2     = (const float*)d_in[6];
    const float *bp         = (const float*)d_in[7];
    const float *ssm_ln_g   = (const float*)d_in[8];
    const float *ssm_ln_b   = (const float*)d_in[9];
    const float *in_proj_w  = (const float*)d_in[10];
    const float *conv_w     = (const float*)d_in[11];
    const float *conv_b     = (const float*)d_in[12];
    const float *x_proj_w   = (const float*)d_in[13];
    const float *dt_proj_w  = (const float*)d_in[14];
    const float *dt_proj_b  = (const float*)d_in[15];
    const float *A_log      = (const float*)d_in[16];
    const float *Dp         = (const float*)d_in[17];
    const float *out_proj_w = (const float*)d_in[18];
    const float *ln1_g      = (const float*)d_in[19];
    const float *ln1_b      = (const float*)d_in[20];
    const float *qkv_w      = (const float*)d_in[21];
    const float *attn_proj_w= (const float*)d_in[22];
    const float *attn_proj_b= (const float*)d_in[23];
    const float *ln2_g      = (const float*)d_in[24];
    const float *ln2_b      = (const float*)d_in[25];
    const float *mlp_w1     = (const float*)d_in[26];
    const float *mlp_b1     = (const float*)d_in[27];
    const float *mlp_w2     = (const float*)d_in[28];
    const float *mlp_b2     = (const float*)d_in[29];
    float* outp             = (float*)d_out;

    const int nb   = in_sizes[0] / 4352;
    const int Ttot = nb * 17;
    const int mT   = (Ttot + 127) / 128;

    __nv_bfloat16 *bufA = 0, *bufB = 0, *bufC = 0, *bufD = 0, *wt = 0;
    float *res1 = 0, *res2 = 0, *x1 = 0, *tmpf = 0;
    cudaGetSymbolAddress((void**)&bufA, g_bufA);
    cudaGetSymbolAddress((void**)&bufB, g_bufB);
    cudaGetSymbolAddress((void**)&bufC, g_bufC);
    cudaGetSymbolAddress((void**)&bufD, g_bufD);
    cudaGetSymbolAddress((void**)&res1, g_res1);
    cudaGetSymbolAddress((void**)&res2, g_res2);
    cudaGetSymbolAddress((void**)&x1,   g_x1);
    cudaGetSymbolAddress((void**)&tmpf, g_tmpf);
    cudaGetSymbolAddress((void**)&wt,   g_wt);

    __nv_bfloat16* wt_gcn1 = wt;
    __nv_bfloat16* wt_gcn2 = wt + 131072;
    __nv_bfloat16* wt_inp  = wt + 262144;
    __nv_bfloat16* wt_outp = wt + 524288;
    __nv_bfloat16* wt_qkv  = wt + 655360;
    __nv_bfloat16* wt_attn = wt + 851968;
    __nv_bfloat16* wt_mlp1 = wt + 917504;
    __nv_bfloat16* wt_mlp2 = wt + 1179648;

    const int scan_smem = SCAN_SMEM_FLOATS * 4;
    cudaFuncSetAttribute(k_scan, cudaFuncAttributeMaxDynamicSharedMemorySize, scan_smem);
    cudaFuncSetAttribute(k_attn, cudaFuncAttributeMaxDynamicSharedMemorySize, 13056*4);

    WT8 w;
    w.W[0]=gcn_w1;      w.O[0]=wt_gcn1; w.K[0]=256;  w.N[0]=512;
    w.W[1]=gcn_w2;      w.O[1]=wt_gcn2; w.K[1]=512;  w.N[1]=256;
    w.W[2]=in_proj_w;   w.O[2]=wt_inp;  w.K[2]=256;  w.N[2]=1024;
    w.W[3]=out_proj_w;  w.O[3]=wt_outp; w.K[3]=512;  w.N[3]=256;
    w.W[4]=qkv_w;       w.O[4]=wt_qkv;  w.K[4]=256;  w.N[4]=768;
    w.W[5]=attn_proj_w; w.O[5]=wt_attn; w.K[5]=256;  w.N[5]=256;
    w.W[6]=mlp_w1;      w.O[6]=wt_mlp1; w.K[6]=256;  w.N[6]=1024;
    w.W[7]=mlp_w2;      w.O[7]=wt_mlp2; w.K[7]=1024; w.N[7]=256;
    {
        int acc = 0;
        for (int i = 0; i < 8; ++i) {
            w.tileStart[i] = acc;
            acc += (w.K[i]/32)*(w.N[i]/32);
        }
        w.tileStart[8] = acc;
        dim3 tb(32, 8);
        const int half = acc / 2;
        k_wt_all<<<half, tb>>>(w, 0);
        k_wt_all<<<acc - half, tb>>>(w, half);
    }

    // Stage A: GCN
    k_pre<<<nb, 256>>>(x, gcn_ln_g, gcn_ln_b);
    GP p1 = { bufD, wt_gcn1, gcn_b1, 0, 0, 0, 0, 0, bufC };
    gemm_tc<256,512,1><<<dim3(4, mT), 256>>>(p1, Ttot);
    k_mid1<<<nb, 256>>>();
    GP p2 = { bufB, wt_gcn2, gcn_b2, x, 0, 0, 0, res1, 0 };
    gemm_tc<512,256,2><<<dim3(2, mT), 256>>>(p2, Ttot);

    // Stage B: SSM
    k_mid2<<<nb, 256>>>(bp, ssm_ln_g, ssm_ln_b);
    GP p3 = { bufD, wt_inp, 0, 0, 0, conv_w, conv_b, 0, bufA };
    gemm_tc<256,1024,4><<<dim3(8, mT), 256>>>(p3, Ttot);
    k_scan<<<nb, 512, scan_smem>>>(x_proj_w, dt_proj_w, dt_proj_b, A_log, Dp);
    GP p4 = { bufC, wt_outp, 0, 0, 0, 0, 0, tmpf, 0 };
    gemm_tc<512,256,3><<<dim3(2, mT), 256>>>(p4, Ttot);
    k_mid3<<<nb, 256>>>(ln1_g, ln1_b);

    // Stage C: attention
    GP p5 = { bufD, wt_qkv, 0, 0, 0, 0, 0, 0, bufB };
    gemm_tc<256,768,0><<<dim3(6, mT), 256>>>(p5, Ttot);
    k_attn<<<nb, 512, 13056*4>>>();
    GP p6 = { bufD, wt_attn, attn_proj_b, res2, 0, 0, 0, x1, 0 };
    gemm_tc<256,256,2><<<dim3(2, mT), 256>>>(p6, Ttot);

    // Stage D: MLP
    k_ln2<<<nb, 256>>>(ln2_g, ln2_b);
    GP p7 = { bufD, wt_mlp1, mlp_b1, 0, 0, 0, 0, 0, bufA };
    gemm_tc<256,1024,1><<<dim3(8, mT), 256>>>(p7, Ttot);
    GP p8 = { bufA, wt_mlp2, mlp_b2, x1, res2, 0, 0, outp, 0 };
    gemm_tc<1024,256,5><<<dim3(2, mT), 256>>>(p8, Ttot);
}